// round 1
// baseline (speedup 1.0000x reference)
#include <cuda_runtime.h>
#include <cuda_bf16.h>
#include <math_constants.h>

// Problem constants (shapes fixed by setup_inputs)
#define NMAX 30000
#define EMAX 480000
#define GNUM 64
#define HF 64
#define HEADS 8
#define MLPD 256

// ------------------------- device scratch -------------------------
__device__ float g_h   [NMAX * HF];          // projected features
__device__ float g_feat[NMAX * HEADS * HF];  // fc output (layer1: 512 cols; layer2 reuses first 64)
__device__ float g_res [NMAX * HEADS * HF];  // residual fc output (layer1)
__device__ float g_el  [NMAX * HEADS];
__device__ float g_er  [NMAX * HEADS];
__device__ float g_h2  [NMAX * HF];
__device__ float g_h3  [NMAX * HF];
__device__ int   g_indeg [NMAX];             // also reused as scatter cursor
__device__ int   g_rowptr[NMAX + 1];
__device__ int   g_eidx  [EMAX];
__device__ float g_hg  [GNUM * HF];
__device__ float g_pool[GNUM * HF];

// ------------------------- small utils -------------------------
__global__ void k_zero_f(float* p, int n) {
    int i = blockIdx.x * blockDim.x + threadIdx.x;
    if (i < n) p[i] = 0.f;
}
__global__ void k_zero_i(int* p, int n) {
    int i = blockIdx.x * blockDim.x + threadIdx.x;
    if (i < n) p[i] = 0;
}

// ------------------------- CSR build -------------------------
__global__ void k_hist(const int* __restrict__ dst, int* __restrict__ indeg, int E) {
    int e = blockIdx.x * blockDim.x + threadIdx.x;
    if (e < E) atomicAdd(&indeg[dst[e]], 1);
}

// single-block exclusive scan of indeg -> rowptr (n up to 30720)
__global__ void k_scan(const int* __restrict__ indeg, int* __restrict__ rowptr, int n) {
    __shared__ int part[1024];
    int t = threadIdx.x;
    int chunk = (n + 1023) / 1024;
    int base = t * chunk;
    int s = 0;
    for (int i = 0; i < chunk; i++) {
        int idx = base + i;
        if (idx < n) s += indeg[idx];
    }
    part[t] = s;
    __syncthreads();
    for (int off = 1; off < 1024; off <<= 1) {
        int v = (t >= off) ? part[t - off] : 0;
        __syncthreads();
        part[t] += v;
        __syncthreads();
    }
    int run = (t == 0) ? 0 : part[t - 1];  // exclusive prefix
    for (int i = 0; i < chunk; i++) {
        int idx = base + i;
        if (idx < n) { rowptr[idx] = run; run += indeg[idx]; }
    }
    if (t == 1023) rowptr[n] = run;
}

__global__ void k_scatter(const int* __restrict__ dst, const int* __restrict__ rowptr,
                          int* __restrict__ cursor, int* __restrict__ eidx, int E) {
    int e = blockIdx.x * blockDim.x + threadIdx.x;
    if (e < E) {
        int d = dst[e];
        int pos = atomicAdd(&cursor[d], 1);
        eidx[rowptr[d] + pos] = e;
    }
}

// ------------------------- GEMM: C[M,KOUT] = A[M,64] @ W[64,KOUT] (+bias) -------------------------
template <int KOUT, bool BIAS>
__global__ void k_gemm64(const float* __restrict__ A, const float* __restrict__ W,
                         const float* __restrict__ bias, float* __restrict__ C, int M) {
    __shared__ float As[64][65];
    __shared__ float Ws[64][64];
    int m0 = blockIdx.x * 64;
    int n0 = blockIdx.y * 64;
    int t = threadIdx.x;  // 256 threads

    // load A tile (float4), zero-pad OOB rows
    for (int i = t; i < 1024; i += 256) {
        int r = i >> 4, c = (i & 15) << 2;
        int row = m0 + r;
        float4 v = (row < M) ? *(const float4*)&A[(size_t)row * 64 + c]
                             : make_float4(0.f, 0.f, 0.f, 0.f);
        As[r][c] = v.x; As[r][c + 1] = v.y; As[r][c + 2] = v.z; As[r][c + 3] = v.w;
    }
    // load W tile
    for (int i = t; i < 1024; i += 256) {
        int k = i >> 4, c = (i & 15) << 2;
        *(float4*)&Ws[k][c] = *(const float4*)&W[(size_t)k * KOUT + n0 + c];
    }
    __syncthreads();

    int tx = t & 15, ty = t >> 4;
    float acc[4][4] = {};
#pragma unroll 16
    for (int k = 0; k < 64; k++) {
        float a0 = As[ty * 4 + 0][k];
        float a1 = As[ty * 4 + 1][k];
        float a2 = As[ty * 4 + 2][k];
        float a3 = As[ty * 4 + 3][k];
        float4 b = *(float4*)&Ws[k][tx * 4];
        acc[0][0] += a0 * b.x; acc[0][1] += a0 * b.y; acc[0][2] += a0 * b.z; acc[0][3] += a0 * b.w;
        acc[1][0] += a1 * b.x; acc[1][1] += a1 * b.y; acc[1][2] += a1 * b.z; acc[1][3] += a1 * b.w;
        acc[2][0] += a2 * b.x; acc[2][1] += a2 * b.y; acc[2][2] += a2 * b.z; acc[2][3] += a2 * b.w;
        acc[3][0] += a3 * b.x; acc[3][1] += a3 * b.y; acc[3][2] += a3 * b.z; acc[3][3] += a3 * b.w;
    }
    float4 bv = make_float4(0.f, 0.f, 0.f, 0.f);
    if (BIAS) bv = *(const float4*)&bias[n0 + tx * 4];
#pragma unroll
    for (int i = 0; i < 4; i++) {
        int row = m0 + ty * 4 + i;
        if (row < M) {
            float4 o;
            o.x = acc[i][0] + bv.x; o.y = acc[i][1] + bv.y;
            o.z = acc[i][2] + bv.z; o.w = acc[i][3] + bv.w;
            *(float4*)&C[(size_t)row * KOUT + n0 + tx * 4] = o;
        }
    }
}

// ------------------------- attention coefficients -------------------------
// el[n,h] = <feat[n,h,:], al[h,:]> ; er likewise. One warp per (node, head).
template <int H>
__global__ void k_attn(const float* __restrict__ feat, const float* __restrict__ al,
                       const float* __restrict__ ar, float* __restrict__ el,
                       float* __restrict__ er, int N) {
    int node = blockIdx.x;
    int w = threadIdx.x >> 5, lane = threadIdx.x & 31;
    const float* f = feat + (size_t)node * (H * 64) + w * 64;
    float2 fv = *(const float2*)&f[lane * 2];
    float2 av = *(const float2*)&al[w * 64 + lane * 2];
    float2 rv = *(const float2*)&ar[w * 64 + lane * 2];
    float sl = fv.x * av.x + fv.y * av.y;
    float sr = fv.x * rv.x + fv.y * rv.y;
#pragma unroll
    for (int o = 16; o; o >>= 1) {
        sl += __shfl_xor_sync(~0u, sl, o);
        sr += __shfl_xor_sync(~0u, sr, o);
    }
    if (lane == 0) {
        el[node * H + w] = sl;
        er[node * H + w] = sr;
    }
}

// ------------------------- GAT aggregation + residual + ELU + LN + head-mean -------------------------
// One block per dst node, one warp per head. Each lane owns dims {2*lane, 2*lane+1}.
template <int H>
__global__ void k_gat_agg(const int* __restrict__ src, const float* __restrict__ feat,
                          const float* __restrict__ el, const float* __restrict__ er,
                          const float* __restrict__ res,       // [N,H*64] or null
                          const float* __restrict__ resid_h,   // identity residual [N,64] (used if res==null)
                          const float* __restrict__ bias,      // [H*64]
                          const int* __restrict__ rowptr, const int* __restrict__ eidx,
                          float* __restrict__ out, int N) {
    int dn = blockIdx.x;
    int h = threadIdx.x >> 5, lane = threadIdx.x & 31;
    int rs = rowptr[dn], re = rowptr[dn + 1];
    int deg = re - rs;
    float er_d = er[dn * H + h];

    // pass A: max over incoming edges
    float m = -CUDART_INF_F;
    for (int k = lane; k < deg; k += 32) {
        int e = eidx[rs + k];
        float x = el[src[e] * H + h] + er_d;
        x = x > 0.f ? x : 0.2f * x;
        m = fmaxf(m, x);
    }
#pragma unroll
    for (int o = 16; o; o >>= 1) m = fmaxf(m, __shfl_xor_sync(~0u, m, o));

    // pass B: softmax denominator
    float den = 0.f;
    for (int k = lane; k < deg; k += 32) {
        int e = eidx[rs + k];
        float x = el[src[e] * H + h] + er_d;
        x = x > 0.f ? x : 0.2f * x;
        den += __expf(x - m);
    }
#pragma unroll
    for (int o = 16; o; o >>= 1) den += __shfl_xor_sync(~0u, den, o);
    float inv = (deg > 0) ? 1.f / den : 0.f;

    // pass C: weighted feature gather (all lanes walk edges together)
    float a0 = 0.f, a1 = 0.f;
    for (int k = 0; k < deg; k++) {
        int e = eidx[rs + k];
        int s = src[e];
        float x = el[s * H + h] + er_d;
        x = x > 0.f ? x : 0.2f * x;
        float w = __expf(x - m) * inv;
        float2 f = *(const float2*)&feat[(size_t)s * (H * 64) + h * 64 + lane * 2];
        a0 += w * f.x;
        a1 += w * f.y;
    }

    // residual + bias + ELU
    float r0, r1;
    if (res) {
        float2 rv = *(const float2*)&res[(size_t)dn * (H * 64) + h * 64 + lane * 2];
        r0 = rv.x; r1 = rv.y;
    } else {
        float2 rv = *(const float2*)&resid_h[(size_t)dn * 64 + lane * 2];
        r0 = rv.x; r1 = rv.y;
    }
    float v0 = a0 + r0 + bias[h * 64 + lane * 2];
    float v1 = a1 + r1 + bias[h * 64 + lane * 2 + 1];
    v0 = v0 > 0.f ? v0 : expm1f(v0);
    v1 = v1 > 0.f ? v1 : expm1f(v1);

    // LayerNorm over 64 dims within the warp
    float s = v0 + v1;
#pragma unroll
    for (int o = 16; o; o >>= 1) s += __shfl_xor_sync(~0u, s, o);
    float mu = s * (1.f / 64.f);
    float d0 = v0 - mu, d1 = v1 - mu;
    float q = d0 * d0 + d1 * d1;
#pragma unroll
    for (int o = 16; o; o >>= 1) q += __shfl_xor_sync(~0u, q, o);
    float sc = rsqrtf(q * (1.f / 64.f) + 1e-5f);
    float o0 = d0 * sc, o1 = d1 * sc;

    if (H == 1) {
        out[(size_t)dn * 64 + lane * 2] = o0;
        out[(size_t)dn * 64 + lane * 2 + 1] = o1;
    } else {
        __shared__ float sh[H][64];
        sh[h][lane * 2] = o0;
        sh[h][lane * 2 + 1] = o1;
        __syncthreads();
        if (threadIdx.x < 64) {
            float acc = 0.f;
#pragma unroll
            for (int j = 0; j < H; j++) acc += sh[j][threadIdx.x];
            out[(size_t)dn * 64 + threadIdx.x] = acc * (1.f / H);
        }
    }
}

// ------------------------- graph pooling (segment sum) -------------------------
__global__ void k_pool(const float* __restrict__ x, const int* __restrict__ gid,
                       float* __restrict__ out, int N) {
    int i = blockIdx.x * blockDim.x + threadIdx.x;
    if (i < N * 64) {
        int node = i >> 6, f = i & 63;
        atomicAdd(&out[gid[node] * 64 + f], x[i]);
    }
}

// hg[g,:] += leaky_relu(p[g,:] @ W + b, 0.01)
__global__ void k_hg_update(const float* __restrict__ p, const float* __restrict__ W,
                            const float* __restrict__ b, float* __restrict__ hg) {
    int g = blockIdx.x, f = threadIdx.x;  // 64 x 64
    __shared__ float pr[64];
    pr[f] = p[g * 64 + f];
    __syncthreads();
    float s = b[f];
#pragma unroll 16
    for (int k = 0; k < 64; k++) s += pr[k] * W[k * 64 + f];
    s = s > 0.f ? s : 0.01f * s;
    hg[g * 64 + f] += s;
}

// ------------------------- fused MLP head -------------------------
__global__ void k_mlp(const float* __restrict__ hg, const float* __restrict__ mW0,
                      const float* __restrict__ mb0, const float* __restrict__ mW1,
                      const float* __restrict__ mb1, const float* __restrict__ mW2,
                      const float* __restrict__ mb2, float* __restrict__ out) {
    int g = blockIdx.x;
    int t = threadIdx.x;  // 256
    __shared__ float x0[64], x1[256];
    if (t < 64) x0[t] = hg[g * 64 + t];
    __syncthreads();
    float s = mb0[t];
#pragma unroll 16
    for (int k = 0; k < 64; k++) s += x0[k] * mW0[k * 256 + t];
    x1[t] = fmaxf(s, 0.f);
    __syncthreads();
    s = mb1[t];
#pragma unroll 16
    for (int k = 0; k < 256; k++) s += x1[k] * mW1[k * 256 + t];
    float y = fmaxf(s, 0.f);
    __syncthreads();
    x1[t] = y;
    __syncthreads();
    s = mb2[t];
#pragma unroll 16
    for (int k = 0; k < 256; k++) s += x1[k] * mW2[k * 256 + t];
    out[g * 256 + t] = s;
}

// ------------------------- host launch -------------------------
extern "C" void kernel_launch(void* const* d_in, const int* in_sizes, int n_in,
                              void* d_out, int out_size) {
    const float* X     = (const float*)d_in[0];
    const int*   src   = (const int*)d_in[1];
    const int*   dst   = (const int*)d_in[2];
    const int*   gid   = (const int*)d_in[3];
    const float* projW = (const float*)d_in[4];
    const float* projb = (const float*)d_in[5];
    const float* fcW1  = (const float*)d_in[6];
    const float* al1   = (const float*)d_in[7];
    const float* ar1   = (const float*)d_in[8];
    const float* resW1 = (const float*)d_in[9];
    const float* b1    = (const float*)d_in[10];
    const float* fcW2  = (const float*)d_in[11];
    const float* al2   = (const float*)d_in[12];
    const float* ar2   = (const float*)d_in[13];
    const float* b2    = (const float*)d_in[14];
    const float* gW1   = (const float*)d_in[15];
    const float* gb1   = (const float*)d_in[16];
    const float* gW2   = (const float*)d_in[17];
    const float* gb2   = (const float*)d_in[18];
    const float* mW0   = (const float*)d_in[19];
    const float* mb0   = (const float*)d_in[20];
    const float* mW1   = (const float*)d_in[21];
    const float* mb1   = (const float*)d_in[22];
    const float* mW2   = (const float*)d_in[23];
    const float* mb2   = (const float*)d_in[24];
    float* out = (float*)d_out;

    int N = in_sizes[0] / HF;
    int E = in_sizes[1];
    if (N > NMAX) N = NMAX;
    if (E > EMAX) E = EMAX;

    float *p_h, *p_feat, *p_res, *p_el, *p_er, *p_h2, *p_h3, *p_hg, *p_pool;
    int *p_indeg, *p_rowptr, *p_eidx;
    cudaGetSymbolAddress((void**)&p_h, g_h);
    cudaGetSymbolAddress((void**)&p_feat, g_feat);
    cudaGetSymbolAddress((void**)&p_res, g_res);
    cudaGetSymbolAddress((void**)&p_el, g_el);
    cudaGetSymbolAddress((void**)&p_er, g_er);
    cudaGetSymbolAddress((void**)&p_h2, g_h2);
    cudaGetSymbolAddress((void**)&p_h3, g_h3);
    cudaGetSymbolAddress((void**)&p_hg, g_hg);
    cudaGetSymbolAddress((void**)&p_pool, g_pool);
    cudaGetSymbolAddress((void**)&p_indeg, g_indeg);
    cudaGetSymbolAddress((void**)&p_rowptr, g_rowptr);
    cudaGetSymbolAddress((void**)&p_eidx, g_eidx);

    int rowTiles = (N + 63) / 64;
    int eBlocks = (E + 255) / 256;
    int nfBlocks = (N * 64 + 255) / 256;

    // --- CSR build (depends only on dst; shared by both layers) ---
    k_zero_i<<<(N + 255) / 256, 256>>>(p_indeg, N);
    k_zero_f<<<(GNUM * HF + 255) / 256, 256>>>(p_hg, GNUM * HF);
    k_hist<<<eBlocks, 256>>>(dst, p_indeg, E);
    k_scan<<<1, 1024>>>(p_indeg, p_rowptr, N);
    k_zero_i<<<(N + 255) / 256, 256>>>(p_indeg, N);  // reuse as cursor
    k_scatter<<<eBlocks, 256>>>(dst, p_rowptr, p_indeg, p_eidx, E);

    // --- projection + initial pooling ---
    k_gemm64<64, true><<<dim3(rowTiles, 1), 256>>>(X, projW, projb, p_h, N);
    k_pool<<<nfBlocks, 256>>>(p_h, gid, p_hg, N);

    // --- GAT layer 1 (8 heads, linear residual) ---
    k_gemm64<512, false><<<dim3(rowTiles, 8), 256>>>(p_h, fcW1, nullptr, p_feat, N);
    k_gemm64<512, false><<<dim3(rowTiles, 8), 256>>>(p_h, resW1, nullptr, p_res, N);
    k_attn<8><<<N, 256>>>(p_feat, al1, ar1, p_el, p_er, N);
    k_gat_agg<8><<<N, 256>>>(src, p_feat, p_el, p_er, p_res, nullptr, b1,
                             p_rowptr, p_eidx, p_h2, N);
    k_zero_f<<<(GNUM * HF + 255) / 256, 256>>>(p_pool, GNUM * HF);
    k_pool<<<nfBlocks, 256>>>(p_h2, gid, p_pool, N);
    k_hg_update<<<GNUM, 64>>>(p_pool, gW1, gb1, p_hg);

    // --- GAT layer 2 (1 head, identity residual) ---
    k_gemm64<64, false><<<dim3(rowTiles, 1), 256>>>(p_h2, fcW2, nullptr, p_feat, N);
    k_attn<1><<<N, 32>>>(p_feat, al2, ar2, p_el, p_er, N);
    k_gat_agg<1><<<N, 32>>>(src, p_feat, p_el, p_er, nullptr, p_h2, b2,
                            p_rowptr, p_eidx, p_h3, N);
    k_zero_f<<<(GNUM * HF + 255) / 256, 256>>>(p_pool, GNUM * HF);
    k_pool<<<nfBlocks, 256>>>(p_h3, gid, p_pool, N);
    k_hg_update<<<GNUM, 64>>>(p_pool, gW2, gb2, p_hg);

    // --- MLP head ---
    k_mlp<<<GNUM, 256>>>(p_hg, mW0, mb0, mW1, mb1, mW2, mb2, out);
}

// round 2
// speedup vs baseline: 1.0615x; 1.0615x over previous
#include <cuda_runtime.h>
#include <cuda_bf16.h>
#include <math_constants.h>

#define NMAX 30000
#define EMAX 480000
#define GNUM 64
#define HF 64
#define HEADS 8
#define MLPD 256

// ------------------------- device scratch -------------------------
__device__ float g_h   [NMAX * HF];
__device__ float g_feat[NMAX * HEADS * HF];
__device__ float g_res [NMAX * HEADS * HF];
__device__ float g_el  [NMAX * HEADS];
__device__ float g_er  [NMAX * HEADS];
__device__ float g_h2  [NMAX * HF];
__device__ float g_h3  [NMAX * HF];
__device__ float g_w   [EMAX * HEADS];   // per-edge softmax numerators (CSR order)
__device__ float g_den [NMAX * HEADS];
__device__ int   g_indeg [NMAX];
__device__ int   g_cursor[NMAX];
__device__ int   g_rowptr[NMAX + 1];
__device__ int   g_srcs  [EMAX];         // src node per CSR slot
__device__ int   g_pos   [EMAX];         // CSR slot per original edge id
__device__ float g_hg  [GNUM * HF];
__device__ float g_pool[GNUM * HF];
__device__ float g_wl1[HEADS * HF], g_wr1[HEADS * HF];
__device__ float g_wl2[HF],        g_wr2[HF];

// ------------------------- utils -------------------------
__global__ void k_zero_f(float* p, int n) {
    int i = blockIdx.x * blockDim.x + threadIdx.x;
    if (i < n) p[i] = 0.f;
}
__global__ void k_zero_i(int* p, int n) {
    int i = blockIdx.x * blockDim.x + threadIdx.x;
    if (i < n) p[i] = 0;
}

// ------------------------- CSR build -------------------------
__global__ void k_hist(const int* __restrict__ dst, int* __restrict__ indeg, int E) {
    int e = blockIdx.x * blockDim.x + threadIdx.x;
    if (e < E) atomicAdd(&indeg[dst[e]], 1);
}

// single-block coalesced tiled scan (exclusive) of indeg -> rowptr
__global__ void k_scan(const int* __restrict__ indeg, int* __restrict__ rowptr, int n) {
    __shared__ int warpsum[32];
    __shared__ int s_total;
    int t = threadIdx.x, lane = t & 31, w = t >> 5;
    int carry = 0;
    for (int base = 0; base < n; base += 1024) {
        int idx = base + t;
        int v = (idx < n) ? indeg[idx] : 0;
        int x = v;
#pragma unroll
        for (int o = 1; o < 32; o <<= 1) {
            int y = __shfl_up_sync(~0u, x, o);
            if (lane >= o) x += y;
        }
        if (lane == 31) warpsum[w] = x;
        __syncthreads();
        if (w == 0) {
            int y = warpsum[lane];
#pragma unroll
            for (int o = 1; o < 32; o <<= 1) {
                int z = __shfl_up_sync(~0u, y, o);
                if (lane >= o) y += z;
            }
            warpsum[lane] = y;
            if (lane == 31) s_total = y;
        }
        __syncthreads();
        int off = carry + (w ? warpsum[w - 1] : 0);
        if (idx < n) rowptr[idx] = off + x - v;
        carry += s_total;
        __syncthreads();
    }
    if (t == 0) rowptr[n] = carry;
}

// ------------------------- attention weight prep -------------------------
// wl[h,i] = sum_d fcW[i, h*64+d] * al[h,d]   (el = h @ wl_h)
template <int H>
__global__ void k_prep_w(const float* __restrict__ fcW, const float* __restrict__ al,
                         const float* __restrict__ ar, float* __restrict__ wl,
                         float* __restrict__ wr) {
    int t = blockIdx.x * blockDim.x + threadIdx.x;
    if (t >= H * 64) return;
    int h = t >> 6, i = t & 63;
    float sl = 0.f, sr = 0.f;
#pragma unroll 16
    for (int d = 0; d < 64; d++) {
        float v = fcW[i * (H * 64) + h * 64 + d];
        sl += v * al[h * 64 + d];
        sr += v * ar[h * 64 + d];
    }
    wl[h * 64 + i] = sl;
    wr[h * 64 + i] = sr;
}

// el[n,h] = h_row . wl_h  (reads h, NOT feat). One warp per node.
template <int H>
__global__ void k_attn(const float* __restrict__ hfeat, const float* __restrict__ wl,
                       const float* __restrict__ wr, float* __restrict__ el,
                       float* __restrict__ er, int N) {
    __shared__ float swl[H * 64], swr[H * 64];
    int t = threadIdx.x;
    for (int i = t; i < H * 64; i += blockDim.x) { swl[i] = wl[i]; swr[i] = wr[i]; }
    __syncthreads();
    int lane = t & 31;
    int node = blockIdx.x * (blockDim.x >> 5) + (t >> 5);
    if (node >= N) return;
    float2 f = *(const float2*)&hfeat[(size_t)node * 64 + lane * 2];
#pragma unroll
    for (int h = 0; h < H; h++) {
        float sl = f.x * swl[h * 64 + lane * 2] + f.y * swl[h * 64 + lane * 2 + 1];
        float sr = f.x * swr[h * 64 + lane * 2] + f.y * swr[h * 64 + lane * 2 + 1];
#pragma unroll
        for (int o = 16; o; o >>= 1) {
            sl += __shfl_xor_sync(~0u, sl, o);
            sr += __shfl_xor_sync(~0u, sr, o);
        }
        if (lane == 0) { el[node * H + h] = sl; er[node * H + h] = sr; }
    }
}

// ------------------------- edge kernels: exp weights + scatter + denominator -------------------------
// Layer 1 (H=8): assigns CSR slot (fused scatter), stores pos for reuse by layer 2.
__global__ void k_edge1_h8(const int* __restrict__ src, const int* __restrict__ dst,
                           const float* __restrict__ el, const float* __restrict__ er,
                           const int* __restrict__ rowptr, int* __restrict__ cursor,
                           int* __restrict__ srcs, int* __restrict__ pos_out,
                           float* __restrict__ w, float* __restrict__ den, int E) {
    int e = blockIdx.x * blockDim.x + threadIdx.x;
    if (e >= E) return;
    int s = src[e], d = dst[e];
    int pos = rowptr[d] + atomicAdd(&cursor[d], 1);
    pos_out[e] = pos;
    srcs[pos] = s;
    float4 el0 = *(const float4*)&el[s * 8];
    float4 el1 = *(const float4*)&el[s * 8 + 4];
    float4 er0 = *(const float4*)&er[d * 8];
    float4 er1 = *(const float4*)&er[d * 8 + 4];
    float x[8] = {el0.x + er0.x, el0.y + er0.y, el0.z + er0.z, el0.w + er0.w,
                  el1.x + er1.x, el1.y + er1.y, el1.z + er1.z, el1.w + er1.w};
    float4 w0, w1;
    float* wo = (float*)&w0;
#pragma unroll
    for (int h = 0; h < 8; h++) {
        float v = x[h] > 0.f ? x[h] : 0.2f * x[h];
        float ex = __expf(v);
        ((h < 4) ? ((float*)&w0) : ((float*)&w1))[h & 3] = ex;
        atomicAdd(&den[d * 8 + h], ex);
    }
    (void)wo;
    *(float4*)&w[pos * 8] = w0;
    *(float4*)&w[pos * 8 + 4] = w1;
}

// Layer 2 (H=1): reuses the slot map from layer 1.
__global__ void k_edge2_h1(const int* __restrict__ src, const int* __restrict__ dst,
                           const float* __restrict__ el, const float* __restrict__ er,
                           const int* __restrict__ pos_in, float* __restrict__ w,
                           float* __restrict__ den, int E) {
    int e = blockIdx.x * blockDim.x + threadIdx.x;
    if (e >= E) return;
    int s = src[e], d = dst[e];
    float x = el[s] + er[d];
    x = x > 0.f ? x : 0.2f * x;
    float ex = __expf(x);
    w[pos_in[e]] = ex;
    atomicAdd(&den[d], ex);
}

// ------------------------- GEMMs -------------------------
template <int KOUT, bool BIAS>
__global__ void k_gemm64(const float* __restrict__ A, const float* __restrict__ W,
                         const float* __restrict__ bias, float* __restrict__ C, int M) {
    __shared__ float As[64][65];
    __shared__ float Ws[64][64];
    int m0 = blockIdx.x * 64;
    int n0 = blockIdx.y * 64;
    int t = threadIdx.x;
    for (int i = t; i < 1024; i += 256) {
        int r = i >> 4, c = (i & 15) << 2;
        int row = m0 + r;
        float4 v = (row < M) ? *(const float4*)&A[(size_t)row * 64 + c]
                             : make_float4(0.f, 0.f, 0.f, 0.f);
        As[r][c] = v.x; As[r][c + 1] = v.y; As[r][c + 2] = v.z; As[r][c + 3] = v.w;
    }
    for (int i = t; i < 1024; i += 256) {
        int k = i >> 4, c = (i & 15) << 2;
        *(float4*)&Ws[k][c] = *(const float4*)&W[(size_t)k * KOUT + n0 + c];
    }
    __syncthreads();
    int tx = t & 15, ty = t >> 4;
    float acc[4][4] = {};
#pragma unroll 16
    for (int k = 0; k < 64; k++) {
        float a0 = As[ty * 4 + 0][k];
        float a1 = As[ty * 4 + 1][k];
        float a2 = As[ty * 4 + 2][k];
        float a3 = As[ty * 4 + 3][k];
        float4 b = *(float4*)&Ws[k][tx * 4];
        acc[0][0] += a0 * b.x; acc[0][1] += a0 * b.y; acc[0][2] += a0 * b.z; acc[0][3] += a0 * b.w;
        acc[1][0] += a1 * b.x; acc[1][1] += a1 * b.y; acc[1][2] += a1 * b.z; acc[1][3] += a1 * b.w;
        acc[2][0] += a2 * b.x; acc[2][1] += a2 * b.y; acc[2][2] += a2 * b.z; acc[2][3] += a2 * b.w;
        acc[3][0] += a3 * b.x; acc[3][1] += a3 * b.y; acc[3][2] += a3 * b.z; acc[3][3] += a3 * b.w;
    }
    float4 bv = make_float4(0.f, 0.f, 0.f, 0.f);
    if (BIAS) bv = *(const float4*)&bias[n0 + tx * 4];
#pragma unroll
    for (int i = 0; i < 4; i++) {
        int row = m0 + ty * 4 + i;
        if (row < M) {
            float4 o;
            o.x = acc[i][0] + bv.x; o.y = acc[i][1] + bv.y;
            o.z = acc[i][2] + bv.z; o.w = acc[i][3] + bv.w;
            *(float4*)&C[(size_t)row * KOUT + n0 + tx * 4] = o;
        }
    }
}

// fused fc1 + res1: grid.y in [0,16); y<8 -> fcW1->feat, else resW1->res
__global__ void k_gemm_dual(const float* __restrict__ A, const float* __restrict__ W0,
                            const float* __restrict__ W1, float* __restrict__ C0,
                            float* __restrict__ C1, int M) {
    __shared__ float As[64][65];
    __shared__ float Ws[64][64];
    int m0 = blockIdx.x * 64;
    int yy = blockIdx.y;
    const float* W = (yy < 8) ? W0 : W1;
    float* C = (yy < 8) ? C0 : C1;
    int n0 = (yy & 7) * 64;
    int t = threadIdx.x;
    for (int i = t; i < 1024; i += 256) {
        int r = i >> 4, c = (i & 15) << 2;
        int row = m0 + r;
        float4 v = (row < M) ? *(const float4*)&A[(size_t)row * 64 + c]
                             : make_float4(0.f, 0.f, 0.f, 0.f);
        As[r][c] = v.x; As[r][c + 1] = v.y; As[r][c + 2] = v.z; As[r][c + 3] = v.w;
    }
    for (int i = t; i < 1024; i += 256) {
        int k = i >> 4, c = (i & 15) << 2;
        *(float4*)&Ws[k][c] = *(const float4*)&W[(size_t)k * 512 + n0 + c];
    }
    __syncthreads();
    int tx = t & 15, ty = t >> 4;
    float acc[4][4] = {};
#pragma unroll 16
    for (int k = 0; k < 64; k++) {
        float a0 = As[ty * 4 + 0][k];
        float a1 = As[ty * 4 + 1][k];
        float a2 = As[ty * 4 + 2][k];
        float a3 = As[ty * 4 + 3][k];
        float4 b = *(float4*)&Ws[k][tx * 4];
        acc[0][0] += a0 * b.x; acc[0][1] += a0 * b.y; acc[0][2] += a0 * b.z; acc[0][3] += a0 * b.w;
        acc[1][0] += a1 * b.x; acc[1][1] += a1 * b.y; acc[1][2] += a1 * b.z; acc[1][3] += a1 * b.w;
        acc[2][0] += a2 * b.x; acc[2][1] += a2 * b.y; acc[2][2] += a2 * b.z; acc[2][3] += a2 * b.w;
        acc[3][0] += a3 * b.x; acc[3][1] += a3 * b.y; acc[3][2] += a3 * b.z; acc[3][3] += a3 * b.w;
    }
#pragma unroll
    for (int i = 0; i < 4; i++) {
        int row = m0 + ty * 4 + i;
        if (row < M) {
            float4 o = make_float4(acc[i][0], acc[i][1], acc[i][2], acc[i][3]);
            *(float4*)&C[(size_t)row * 512 + n0 + tx * 4] = o;
        }
    }
}

// ------------------------- single-pass aggregation + residual + ELU + LN + mean -------------------------
// H=8: one block per dst node, warp per head, lane owns 2 dims.
__global__ void k_agg8(const int* __restrict__ srcs, const float* __restrict__ feat,
                       const float* __restrict__ w, const float* __restrict__ den,
                       const float* __restrict__ res, const float* __restrict__ bias,
                       const int* __restrict__ rowptr, float* __restrict__ out, int N) {
    int dn = blockIdx.x;
    int h = threadIdx.x >> 5, lane = threadIdx.x & 31;
    int rs = rowptr[dn], deg = rowptr[dn + 1] - rs;
    float inv = (deg > 0) ? 1.f / den[dn * 8 + h] : 0.f;
    float a0 = 0.f, a1 = 0.f;
#pragma unroll 2
    for (int k = 0; k < deg; k++) {
        int s = srcs[rs + k];
        float ww = w[(rs + k) * 8 + h];
        float2 f = *(const float2*)&feat[(size_t)s * 512 + h * 64 + lane * 2];
        a0 += ww * f.x;
        a1 += ww * f.y;
    }
    a0 *= inv; a1 *= inv;
    float2 rv = *(const float2*)&res[(size_t)dn * 512 + h * 64 + lane * 2];
    float v0 = a0 + rv.x + bias[h * 64 + lane * 2];
    float v1 = a1 + rv.y + bias[h * 64 + lane * 2 + 1];
    v0 = v0 > 0.f ? v0 : expm1f(v0);
    v1 = v1 > 0.f ? v1 : expm1f(v1);
    float s = v0 + v1;
#pragma unroll
    for (int o = 16; o; o >>= 1) s += __shfl_xor_sync(~0u, s, o);
    float mu = s * (1.f / 64.f);
    float d0 = v0 - mu, d1 = v1 - mu;
    float q = d0 * d0 + d1 * d1;
#pragma unroll
    for (int o = 16; o; o >>= 1) q += __shfl_xor_sync(~0u, q, o);
    float sc = rsqrtf(q * (1.f / 64.f) + 1e-5f);
    __shared__ float sh[8][64];
    sh[h][lane * 2] = d0 * sc;
    sh[h][lane * 2 + 1] = d1 * sc;
    __syncthreads();
    if (threadIdx.x < 64) {
        float acc = 0.f;
#pragma unroll
        for (int j = 0; j < 8; j++) acc += sh[j][threadIdx.x];
        out[(size_t)dn * 64 + threadIdx.x] = acc * 0.125f;
    }
}

// H=1: 8 nodes per block (warp each), identity residual.
__global__ void k_agg1(const int* __restrict__ srcs, const float* __restrict__ feat,
                       const float* __restrict__ w, const float* __restrict__ den,
                       const float* __restrict__ resid_h, const float* __restrict__ bias,
                       const int* __restrict__ rowptr, float* __restrict__ out, int N) {
    int node = blockIdx.x * 8 + (threadIdx.x >> 5);
    int lane = threadIdx.x & 31;
    if (node >= N) return;
    int rs = rowptr[node], deg = rowptr[node + 1] - rs;
    float inv = (deg > 0) ? 1.f / den[node] : 0.f;
    float a0 = 0.f, a1 = 0.f;
#pragma unroll 2
    for (int k = 0; k < deg; k++) {
        int s = srcs[rs + k];
        float ww = w[rs + k];
        float2 f = *(const float2*)&feat[(size_t)s * 64 + lane * 2];
        a0 += ww * f.x;
        a1 += ww * f.y;
    }
    a0 *= inv; a1 *= inv;
    float2 rv = *(const float2*)&resid_h[(size_t)node * 64 + lane * 2];
    float v0 = a0 + rv.x + bias[lane * 2];
    float v1 = a1 + rv.y + bias[lane * 2 + 1];
    v0 = v0 > 0.f ? v0 : expm1f(v0);
    v1 = v1 > 0.f ? v1 : expm1f(v1);
    float s = v0 + v1;
#pragma unroll
    for (int o = 16; o; o >>= 1) s += __shfl_xor_sync(~0u, s, o);
    float mu = s * (1.f / 64.f);
    float d0 = v0 - mu, d1 = v1 - mu;
    float q = d0 * d0 + d1 * d1;
#pragma unroll
    for (int o = 16; o; o >>= 1) q += __shfl_xor_sync(~0u, q, o);
    float sc = rsqrtf(q * (1.f / 64.f) + 1e-5f);
    out[(size_t)node * 64 + lane * 2] = d0 * sc;
    out[(size_t)node * 64 + lane * 2 + 1] = d1 * sc;
}

// ------------------------- pooling / head -------------------------
__global__ void k_pool(const float* __restrict__ x, const int* __restrict__ gid,
                       float* __restrict__ out, int N) {
    int i = blockIdx.x * blockDim.x + threadIdx.x;
    if (i < N * 64) {
        int node = i >> 6, f = i & 63;
        atomicAdd(&out[gid[node] * 64 + f], x[i]);
    }
}

__global__ void k_hg_update(const float* __restrict__ p, const float* __restrict__ W,
                            const float* __restrict__ b, float* __restrict__ hg) {
    int g = blockIdx.x, f = threadIdx.x;
    __shared__ float pr[64];
    pr[f] = p[g * 64 + f];
    __syncthreads();
    float s = b[f];
#pragma unroll 16
    for (int k = 0; k < 64; k++) s += pr[k] * W[k * 64 + f];
    s = s > 0.f ? s : 0.01f * s;
    hg[g * 64 + f] += s;
}

__global__ void k_mlp(const float* __restrict__ hg, const float* __restrict__ mW0,
                      const float* __restrict__ mb0, const float* __restrict__ mW1,
                      const float* __restrict__ mb1, const float* __restrict__ mW2,
                      const float* __restrict__ mb2, float* __restrict__ out) {
    int g = blockIdx.x;
    int t = threadIdx.x;
    __shared__ float x0[64], x1[256];
    if (t < 64) x0[t] = hg[g * 64 + t];
    __syncthreads();
    float s = mb0[t];
#pragma unroll 16
    for (int k = 0; k < 64; k++) s += x0[k] * mW0[k * 256 + t];
    x1[t] = fmaxf(s, 0.f);
    __syncthreads();
    s = mb1[t];
#pragma unroll 16
    for (int k = 0; k < 256; k++) s += x1[k] * mW1[k * 256 + t];
    float y = fmaxf(s, 0.f);
    __syncthreads();
    x1[t] = y;
    __syncthreads();
    s = mb2[t];
#pragma unroll 16
    for (int k = 0; k < 256; k++) s += x1[k] * mW2[k * 256 + t];
    out[g * 256 + t] = s;
}

// ------------------------- host launch -------------------------
extern "C" void kernel_launch(void* const* d_in, const int* in_sizes, int n_in,
                              void* d_out, int out_size) {
    const float* X     = (const float*)d_in[0];
    const int*   src   = (const int*)d_in[1];
    const int*   dst   = (const int*)d_in[2];
    const int*   gid   = (const int*)d_in[3];
    const float* projW = (const float*)d_in[4];
    const float* projb = (const float*)d_in[5];
    const float* fcW1  = (const float*)d_in[6];
    const float* al1   = (const float*)d_in[7];
    const float* ar1   = (const float*)d_in[8];
    const float* resW1 = (const float*)d_in[9];
    const float* b1    = (const float*)d_in[10];
    const float* fcW2  = (const float*)d_in[11];
    const float* al2   = (const float*)d_in[12];
    const float* ar2   = (const float*)d_in[13];
    const float* b2    = (const float*)d_in[14];
    const float* gW1   = (const float*)d_in[15];
    const float* gb1   = (const float*)d_in[16];
    const float* gW2   = (const float*)d_in[17];
    const float* gb2   = (const float*)d_in[18];
    const float* mW0   = (const float*)d_in[19];
    const float* mb0   = (const float*)d_in[20];
    const float* mW1   = (const float*)d_in[21];
    const float* mb1   = (const float*)d_in[22];
    const float* mW2   = (const float*)d_in[23];
    const float* mb2   = (const float*)d_in[24];
    float* out = (float*)d_out;

    int N = in_sizes[0] / HF;
    int E = in_sizes[1];
    if (N > NMAX) N = NMAX;
    if (E > EMAX) E = EMAX;

    float *p_h, *p_feat, *p_res, *p_el, *p_er, *p_h2, *p_h3, *p_hg, *p_pool, *p_w, *p_den;
    float *p_wl1, *p_wr1, *p_wl2, *p_wr2;
    int *p_indeg, *p_cursor, *p_rowptr, *p_srcs, *p_pos;
    cudaGetSymbolAddress((void**)&p_h, g_h);
    cudaGetSymbolAddress((void**)&p_feat, g_feat);
    cudaGetSymbolAddress((void**)&p_res, g_res);
    cudaGetSymbolAddress((void**)&p_el, g_el);
    cudaGetSymbolAddress((void**)&p_er, g_er);
    cudaGetSymbolAddress((void**)&p_h2, g_h2);
    cudaGetSymbolAddress((void**)&p_h3, g_h3);
    cudaGetSymbolAddress((void**)&p_hg, g_hg);
    cudaGetSymbolAddress((void**)&p_pool, g_pool);
    cudaGetSymbolAddress((void**)&p_w, g_w);
    cudaGetSymbolAddress((void**)&p_den, g_den);
    cudaGetSymbolAddress((void**)&p_indeg, g_indeg);
    cudaGetSymbolAddress((void**)&p_cursor, g_cursor);
    cudaGetSymbolAddress((void**)&p_rowptr, g_rowptr);
    cudaGetSymbolAddress((void**)&p_srcs, g_srcs);
    cudaGetSymbolAddress((void**)&p_pos, g_pos);
    cudaGetSymbolAddress((void**)&p_wl1, g_wl1);
    cudaGetSymbolAddress((void**)&p_wr1, g_wr1);
    cudaGetSymbolAddress((void**)&p_wl2, g_wl2);
    cudaGetSymbolAddress((void**)&p_wr2, g_wr2);

    int rowTiles = (N + 63) / 64;
    int eBlocks = (E + 255) / 256;
    int nfBlocks = (N * 64 + 255) / 256;
    int nWarpBlocks = (N + 7) / 8;

    // --- zeros + CSR build ---
    k_zero_i<<<(N + 255) / 256, 256>>>(p_indeg, N);
    k_zero_i<<<(N + 255) / 256, 256>>>(p_cursor, N);
    k_zero_f<<<(N * 8 + 255) / 256, 256>>>(p_den, N * 8);
    k_zero_f<<<(GNUM * HF + 255) / 256, 256>>>(p_hg, GNUM * HF);
    k_hist<<<eBlocks, 256>>>(dst, p_indeg, E);
    k_scan<<<1, 1024>>>(p_indeg, p_rowptr, N);

    // --- attention projection vectors (weights only) ---
    k_prep_w<8><<<2, 256>>>(fcW1, al1, ar1, p_wl1, p_wr1);
    k_prep_w<1><<<1, 64>>>(fcW2, al2, ar2, p_wl2, p_wr2);

    // --- projection + initial pooling ---
    k_gemm64<64, true><<<dim3(rowTiles, 1), 256>>>(X, projW, projb, p_h, N);
    k_pool<<<nfBlocks, 256>>>(p_h, gid, p_hg, N);

    // --- GAT layer 1 ---
    k_attn<8><<<nWarpBlocks, 256>>>(p_h, p_wl1, p_wr1, p_el, p_er, N);
    k_edge1_h8<<<eBlocks, 256>>>(src, dst, p_el, p_er, p_rowptr, p_cursor,
                                 p_srcs, p_pos, p_w, p_den, E);
    k_gemm_dual<<<dim3(rowTiles, 16), 256>>>(p_h, fcW1, resW1, p_feat, p_res, N);
    k_agg8<<<N, 256>>>(p_srcs, p_feat, p_w, p_den, p_res, b1, p_rowptr, p_h2, N);
    k_zero_f<<<(GNUM * HF + 255) / 256, 256>>>(p_pool, GNUM * HF);
    k_pool<<<nfBlocks, 256>>>(p_h2, gid, p_pool, N);
    k_hg_update<<<GNUM, 64>>>(p_pool, gW1, gb1, p_hg);

    // --- GAT layer 2 ---
    k_zero_f<<<(N + 255) / 256, 256>>>(p_den, N);   // reuse den[0:N]
    k_attn<1><<<nWarpBlocks, 256>>>(p_h2, p_wl2, p_wr2, p_el, p_er, N);
    k_edge2_h1<<<eBlocks, 256>>>(src, dst, p_el, p_er, p_pos, p_w, p_den, E);
    k_gemm64<64, false><<<dim3(rowTiles, 1), 256>>>(p_h2, fcW2, nullptr, p_feat, N);
    k_agg1<<<nWarpBlocks, 256>>>(p_srcs, p_feat, p_w, p_den, p_h2, b2, p_rowptr, p_h3, N);
    k_zero_f<<<(GNUM * HF + 255) / 256, 256>>>(p_pool, GNUM * HF);
    k_pool<<<nfBlocks, 256>>>(p_h3, gid, p_pool, N);
    k_hg_update<<<GNUM, 64>>>(p_pool, gW2, gb2, p_hg);

    // --- MLP head ---
    k_mlp<<<GNUM, 256>>>(p_hg, mW0, mb0, mW1, mb1, mW2, mb2, out);
}

// round 3
// speedup vs baseline: 1.3302x; 1.2531x over previous
#include <cuda_runtime.h>
#include <cuda_bf16.h>
#include <math_constants.h>

#define NMAX 30000
#define EMAX 480000
#define GNUM 64
#define HF 64
#define HEADS 8
#define MLPD 256

// ------------------------- device scratch -------------------------
__device__ float g_h   [NMAX * HF];
__device__ float g_agg [NMAX * HEADS * HF];   // per-head aggregated h (layer1) / agg2 (layer2 reuses)
__device__ float g_rst [NMAX * HEADS * HF];   // concat-GEMM output (layer1)
__device__ float g_el  [NMAX * HEADS];
__device__ float g_er  [NMAX * HEADS];
__device__ float g_h2  [NMAX * HF];
__device__ float g_h3  [NMAX * HF];
__device__ float g_w   [EMAX * HEADS];        // per-edge softmax numerators (CSR order)
__device__ int   g_indeg [NMAX];
__device__ int   g_cursor[NMAX];
__device__ int   g_rowptr[NMAX + 1];
__device__ int   g_srcs  [EMAX];
__device__ int   g_pos   [EMAX];
__device__ float g_hg  [GNUM * HF];
__device__ float g_pool[GNUM * HF];
__device__ float g_wl1[HEADS * HF], g_wr1[HEADS * HF];
__device__ float g_wl2[HF],        g_wr2[HF];

// ------------------------- utils -------------------------
__global__ void k_zero_f(float* p, int n) {
    int i = blockIdx.x * blockDim.x + threadIdx.x;
    if (i < n) p[i] = 0.f;
}
__global__ void k_zero_i(int* p, int n) {
    int i = blockIdx.x * blockDim.x + threadIdx.x;
    if (i < n) p[i] = 0;
}

// ------------------------- CSR build -------------------------
__global__ void k_hist(const int* __restrict__ dst, int* __restrict__ indeg, int E) {
    int e = blockIdx.x * blockDim.x + threadIdx.x;
    if (e < E) atomicAdd(&indeg[dst[e]], 1);
}

__global__ void k_scan(const int* __restrict__ indeg, int* __restrict__ rowptr, int n) {
    __shared__ int warpsum[32];
    __shared__ int s_total;
    int t = threadIdx.x, lane = t & 31, w = t >> 5;
    int carry = 0;
    for (int base = 0; base < n; base += 1024) {
        int idx = base + t;
        int v = (idx < n) ? indeg[idx] : 0;
        int x = v;
#pragma unroll
        for (int o = 1; o < 32; o <<= 1) {
            int y = __shfl_up_sync(~0u, x, o);
            if (lane >= o) x += y;
        }
        if (lane == 31) warpsum[w] = x;
        __syncthreads();
        if (w == 0) {
            int y = warpsum[lane];
#pragma unroll
            for (int o = 1; o < 32; o <<= 1) {
                int z = __shfl_up_sync(~0u, y, o);
                if (lane >= o) y += z;
            }
            warpsum[lane] = y;
            if (lane == 31) s_total = y;
        }
        __syncthreads();
        int off = carry + (w ? warpsum[w - 1] : 0);
        if (idx < n) rowptr[idx] = off + x - v;
        carry += s_total;
        __syncthreads();
    }
    if (t == 0) rowptr[n] = carry;
}

// ------------------------- attention weight prep -------------------------
template <int H>
__global__ void k_prep_w(const float* __restrict__ fcW, const float* __restrict__ al,
                         const float* __restrict__ ar, float* __restrict__ wl,
                         float* __restrict__ wr) {
    int t = blockIdx.x * blockDim.x + threadIdx.x;
    if (t >= H * 64) return;
    int h = t >> 6, i = t & 63;
    float sl = 0.f, sr = 0.f;
#pragma unroll 16
    for (int d = 0; d < 64; d++) {
        float v = fcW[i * (H * 64) + h * 64 + d];
        sl += v * al[h * 64 + d];
        sr += v * ar[h * 64 + d];
    }
    wl[h * 64 + i] = sl;
    wr[h * 64 + i] = sr;
}

template <int H>
__global__ void k_attn(const float* __restrict__ hfeat, const float* __restrict__ wl,
                       const float* __restrict__ wr, float* __restrict__ el,
                       float* __restrict__ er, int N) {
    __shared__ float swl[H * 64], swr[H * 64];
    int t = threadIdx.x;
    for (int i = t; i < H * 64; i += blockDim.x) { swl[i] = wl[i]; swr[i] = wr[i]; }
    __syncthreads();
    int lane = t & 31;
    int node = blockIdx.x * (blockDim.x >> 5) + (t >> 5);
    if (node >= N) return;
    float2 f = *(const float2*)&hfeat[(size_t)node * 64 + lane * 2];
#pragma unroll
    for (int h = 0; h < H; h++) {
        float sl = f.x * swl[h * 64 + lane * 2] + f.y * swl[h * 64 + lane * 2 + 1];
        float sr = f.x * swr[h * 64 + lane * 2] + f.y * swr[h * 64 + lane * 2 + 1];
#pragma unroll
        for (int o = 16; o; o >>= 1) {
            sl += __shfl_xor_sync(~0u, sl, o);
            sr += __shfl_xor_sync(~0u, sr, o);
        }
        if (lane == 0) { el[node * H + h] = sl; er[node * H + h] = sr; }
    }
}

// ------------------------- edge kernels -------------------------
// Layer 1 (H=8): CSR slot assignment + exp weights. No den atomics (den folded into agg).
__global__ void k_edge1_h8(const int* __restrict__ src, const int* __restrict__ dst,
                           const float* __restrict__ el, const float* __restrict__ er,
                           const int* __restrict__ rowptr, int* __restrict__ cursor,
                           int* __restrict__ srcs, int* __restrict__ pos_out,
                           float* __restrict__ w, int E) {
    int e = blockIdx.x * blockDim.x + threadIdx.x;
    if (e >= E) return;
    int s = src[e], d = dst[e];
    int pos = rowptr[d] + atomicAdd(&cursor[d], 1);
    pos_out[e] = pos;
    srcs[pos] = s;
    float4 el0 = *(const float4*)&el[s * 8];
    float4 el1 = *(const float4*)&el[s * 8 + 4];
    float4 er0 = *(const float4*)&er[d * 8];
    float4 er1 = *(const float4*)&er[d * 8 + 4];
    float x[8] = {el0.x + er0.x, el0.y + er0.y, el0.z + er0.z, el0.w + er0.w,
                  el1.x + er1.x, el1.y + er1.y, el1.z + er1.z, el1.w + er1.w};
    float4 w0, w1;
#pragma unroll
    for (int h = 0; h < 8; h++) {
        float v = x[h] > 0.f ? x[h] : 0.2f * x[h];
        float ex = __expf(v);
        if (h < 4) ((float*)&w0)[h] = ex; else ((float*)&w1)[h - 4] = ex;
    }
    *(float4*)&w[(size_t)pos * 8] = w0;
    *(float4*)&w[(size_t)pos * 8 + 4] = w1;
}

__global__ void k_edge2_h1(const int* __restrict__ src, const int* __restrict__ dst,
                           const float* __restrict__ el, const float* __restrict__ er,
                           const int* __restrict__ pos_in, float* __restrict__ w, int E) {
    int e = blockIdx.x * blockDim.x + threadIdx.x;
    if (e >= E) return;
    float x = el[src[e]] + er[dst[e]];
    x = x > 0.f ? x : 0.2f * x;
    w[pos_in[e]] = __expf(x);
}

// ------------------------- aggregation: agg[n,h,:] = (sum_e w_e h[src]) / (sum_e w_e) -------------
// One warp per node; lane owns dims {2l,2l+1} of all 8 heads.
__global__ void k_agg_h8(const int* __restrict__ srcs, const float* __restrict__ hfeat,
                         const float* __restrict__ w, const int* __restrict__ rowptr,
                         float* __restrict__ agg, int N) {
    int node = blockIdx.x * 8 + (threadIdx.x >> 5);
    int lane = threadIdx.x & 31;
    if (node >= N) return;
    int rs = rowptr[node], deg = rowptr[node + 1] - rs;
    float ax[8], ay[8], den[8];
#pragma unroll
    for (int h = 0; h < 8; h++) { ax[h] = 0.f; ay[h] = 0.f; den[h] = 0.f; }
    for (int k = 0; k < deg; k++) {
        int s = srcs[rs + k];
        float2 hv = *(const float2*)&hfeat[(size_t)s * 64 + lane * 2];
        float4 w0 = *(const float4*)&w[(size_t)(rs + k) * 8];
        float4 w1 = *(const float4*)&w[(size_t)(rs + k) * 8 + 4];
        const float* ww = (const float*)&w0;
#pragma unroll
        for (int h = 0; h < 4; h++) {
            ax[h] += ww[h] * hv.x; ay[h] += ww[h] * hv.y; den[h] += ww[h];
        }
        const float* ww2 = (const float*)&w1;
#pragma unroll
        for (int h = 0; h < 4; h++) {
            ax[4 + h] += ww2[h] * hv.x; ay[4 + h] += ww2[h] * hv.y; den[4 + h] += ww2[h];
        }
    }
#pragma unroll
    for (int h = 0; h < 8; h++) {
        float inv = (deg > 0) ? 1.f / den[h] : 0.f;
        float2 o = make_float2(ax[h] * inv, ay[h] * inv);
        *(float2*)&agg[(size_t)node * 512 + h * 64 + lane * 2] = o;
    }
}

__global__ void k_agg_h1(const int* __restrict__ srcs, const float* __restrict__ hfeat,
                         const float* __restrict__ w, const int* __restrict__ rowptr,
                         float* __restrict__ agg, int N) {
    int node = blockIdx.x * 8 + (threadIdx.x >> 5);
    int lane = threadIdx.x & 31;
    if (node >= N) return;
    int rs = rowptr[node], deg = rowptr[node + 1] - rs;
    float ax = 0.f, ay = 0.f, den = 0.f;
    for (int k = 0; k < deg; k++) {
        int s = srcs[rs + k];
        float ww = w[rs + k];
        float2 hv = *(const float2*)&hfeat[(size_t)s * 64 + lane * 2];
        ax += ww * hv.x; ay += ww * hv.y; den += ww;
    }
    float inv = (deg > 0) ? 1.f / den : 0.f;
    *(float2*)&agg[(size_t)node * 64 + lane * 2] = make_float2(ax * inv, ay * inv);
}

// ------------------------- GEMMs -------------------------
template <int KOUT, bool BIAS>
__global__ void k_gemm64(const float* __restrict__ A, const float* __restrict__ W,
                         const float* __restrict__ bias, float* __restrict__ C, int M) {
    __shared__ float As[64][65];
    __shared__ float Ws[64][64];
    int m0 = blockIdx.x * 64;
    int n0 = blockIdx.y * 64;
    int t = threadIdx.x;
    for (int i = t; i < 1024; i += 256) {
        int r = i >> 4, c = (i & 15) << 2;
        int row = m0 + r;
        float4 v = (row < M) ? *(const float4*)&A[(size_t)row * 64 + c]
                             : make_float4(0.f, 0.f, 0.f, 0.f);
        As[r][c] = v.x; As[r][c + 1] = v.y; As[r][c + 2] = v.z; As[r][c + 3] = v.w;
    }
    for (int i = t; i < 1024; i += 256) {
        int k = i >> 4, c = (i & 15) << 2;
        *(float4*)&Ws[k][c] = *(const float4*)&W[(size_t)k * KOUT + n0 + c];
    }
    __syncthreads();
    int tx = t & 15, ty = t >> 4;
    float acc[4][4] = {};
#pragma unroll 16
    for (int k = 0; k < 64; k++) {
        float a0 = As[ty * 4 + 0][k];
        float a1 = As[ty * 4 + 1][k];
        float a2 = As[ty * 4 + 2][k];
        float a3 = As[ty * 4 + 3][k];
        float4 b = *(float4*)&Ws[k][tx * 4];
        acc[0][0] += a0 * b.x; acc[0][1] += a0 * b.y; acc[0][2] += a0 * b.z; acc[0][3] += a0 * b.w;
        acc[1][0] += a1 * b.x; acc[1][1] += a1 * b.y; acc[1][2] += a1 * b.z; acc[1][3] += a1 * b.w;
        acc[2][0] += a2 * b.x; acc[2][1] += a2 * b.y; acc[2][2] += a2 * b.z; acc[2][3] += a2 * b.w;
        acc[3][0] += a3 * b.x; acc[3][1] += a3 * b.y; acc[3][2] += a3 * b.z; acc[3][3] += a3 * b.w;
    }
    float4 bv = make_float4(0.f, 0.f, 0.f, 0.f);
    if (BIAS) bv = *(const float4*)&bias[n0 + tx * 4];
#pragma unroll
    for (int i = 0; i < 4; i++) {
        int row = m0 + ty * 4 + i;
        if (row < M) {
            float4 o;
            o.x = acc[i][0] + bv.x; o.y = acc[i][1] + bv.y;
            o.z = acc[i][2] + bv.z; o.w = acc[i][3] + bv.w;
            *(float4*)&C[(size_t)row * KOUT + n0 + tx * 4] = o;
        }
    }
}

// Layer-1 concat GEMM: rst[n, h*64+c] = agg[n,h,:]@fcW1[:,h*64+c] + h[n,:]@resW1[:,h*64+c]
// grid = (rowTiles, 8). Two K-chunks reuse smem.
__global__ void k_gemm_cat1(const float* __restrict__ agg, const float* __restrict__ hfeat,
                            const float* __restrict__ fcW1, const float* __restrict__ resW1,
                            float* __restrict__ rst, int M) {
    __shared__ float As[64][65];
    __shared__ float Ws[64][64];
    int m0 = blockIdx.x * 64;
    int hb = blockIdx.y;       // head
    int t = threadIdx.x;
    int tx = t & 15, ty = t >> 4;
    float acc[4][4] = {};
#pragma unroll
    for (int chunk = 0; chunk < 2; chunk++) {
        const float* Aap = chunk ? hfeat : agg;
        size_t astride = chunk ? 64 : 512;
        size_t aoff = chunk ? 0 : (size_t)hb * 64;
        const float* Wp = chunk ? resW1 : fcW1;
        for (int i = t; i < 1024; i += 256) {
            int r = i >> 4, c = (i & 15) << 2;
            int row = m0 + r;
            float4 v = (row < M) ? *(const float4*)&Aap[(size_t)row * astride + aoff + c]
                                 : make_float4(0.f, 0.f, 0.f, 0.f);
            As[r][c] = v.x; As[r][c + 1] = v.y; As[r][c + 2] = v.z; As[r][c + 3] = v.w;
        }
        for (int i = t; i < 1024; i += 256) {
            int k = i >> 4, c = (i & 15) << 2;
            *(float4*)&Ws[k][c] = *(const float4*)&Wp[(size_t)k * 512 + hb * 64 + c];
        }
        __syncthreads();
#pragma unroll 16
        for (int k = 0; k < 64; k++) {
            float a0 = As[ty * 4 + 0][k];
            float a1 = As[ty * 4 + 1][k];
            float a2 = As[ty * 4 + 2][k];
            float a3 = As[ty * 4 + 3][k];
            float4 b = *(float4*)&Ws[k][tx * 4];
            acc[0][0] += a0 * b.x; acc[0][1] += a0 * b.y; acc[0][2] += a0 * b.z; acc[0][3] += a0 * b.w;
            acc[1][0] += a1 * b.x; acc[1][1] += a1 * b.y; acc[1][2] += a1 * b.z; acc[1][3] += a1 * b.w;
            acc[2][0] += a2 * b.x; acc[2][1] += a2 * b.y; acc[2][2] += a2 * b.z; acc[2][3] += a2 * b.w;
            acc[3][0] += a3 * b.x; acc[3][1] += a3 * b.y; acc[3][2] += a3 * b.z; acc[3][3] += a3 * b.w;
        }
        __syncthreads();
    }
#pragma unroll
    for (int i = 0; i < 4; i++) {
        int row = m0 + ty * 4 + i;
        if (row < M) {
            float4 o = make_float4(acc[i][0], acc[i][1], acc[i][2], acc[i][3]);
            *(float4*)&rst[(size_t)row * 512 + hb * 64 + tx * 4] = o;
        }
    }
}

// Layer-1 epilogue: +bias, ELU, per-head LN, head-mean -> h2
__global__ void k_epi1(const float* __restrict__ rst, const float* __restrict__ bias,
                       float* __restrict__ out, int N) {
    int dn = blockIdx.x;
    int h = threadIdx.x >> 5, lane = threadIdx.x & 31;
    float2 rv = *(const float2*)&rst[(size_t)dn * 512 + h * 64 + lane * 2];
    float v0 = rv.x + bias[h * 64 + lane * 2];
    float v1 = rv.y + bias[h * 64 + lane * 2 + 1];
    v0 = v0 > 0.f ? v0 : expm1f(v0);
    v1 = v1 > 0.f ? v1 : expm1f(v1);
    float s = v0 + v1;
#pragma unroll
    for (int o = 16; o; o >>= 1) s += __shfl_xor_sync(~0u, s, o);
    float mu = s * (1.f / 64.f);
    float d0 = v0 - mu, d1 = v1 - mu;
    float q = d0 * d0 + d1 * d1;
#pragma unroll
    for (int o = 16; o; o >>= 1) q += __shfl_xor_sync(~0u, q, o);
    float sc = rsqrtf(q * (1.f / 64.f) + 1e-5f);
    __shared__ float sh[8][64];
    sh[h][lane * 2] = d0 * sc;
    sh[h][lane * 2 + 1] = d1 * sc;
    __syncthreads();
    if (threadIdx.x < 64) {
        float acc = 0.f;
#pragma unroll
        for (int j = 0; j < 8; j++) acc += sh[j][threadIdx.x];
        out[(size_t)dn * 64 + threadIdx.x] = acc * 0.125f;
    }
}

// Layer-2 GEMM + identity residual + bias + ELU + LN fused -> h3
__global__ void k_gemm_epi2(const float* __restrict__ agg2, const float* __restrict__ fcW2,
                            const float* __restrict__ h2, const float* __restrict__ bias,
                            float* __restrict__ h3, int M) {
    __shared__ float As[64][65];
    __shared__ float Ws[64][64];
    __shared__ float rsum[64][17];
    __shared__ float rsq [64][17];
    __shared__ float stats[64][2];
    int m0 = blockIdx.x * 64;
    int t = threadIdx.x;
    for (int i = t; i < 1024; i += 256) {
        int r = i >> 4, c = (i & 15) << 2;
        int row = m0 + r;
        float4 v = (row < M) ? *(const float4*)&agg2[(size_t)row * 64 + c]
                             : make_float4(0.f, 0.f, 0.f, 0.f);
        As[r][c] = v.x; As[r][c + 1] = v.y; As[r][c + 2] = v.z; As[r][c + 3] = v.w;
    }
    for (int i = t; i < 1024; i += 256) {
        int k = i >> 4, c = (i & 15) << 2;
        *(float4*)&Ws[k][c] = *(const float4*)&fcW2[(size_t)k * 64 + c];
    }
    __syncthreads();
    int tx = t & 15, ty = t >> 4;
    float acc[4][4] = {};
#pragma unroll 16
    for (int k = 0; k < 64; k++) {
        float a0 = As[ty * 4 + 0][k];
        float a1 = As[ty * 4 + 1][k];
        float a2 = As[ty * 4 + 2][k];
        float a3 = As[ty * 4 + 3][k];
        float4 b = *(float4*)&Ws[k][tx * 4];
        acc[0][0] += a0 * b.x; acc[0][1] += a0 * b.y; acc[0][2] += a0 * b.z; acc[0][3] += a0 * b.w;
        acc[1][0] += a1 * b.x; acc[1][1] += a1 * b.y; acc[1][2] += a1 * b.z; acc[1][3] += a1 * b.w;
        acc[2][0] += a2 * b.x; acc[2][1] += a2 * b.y; acc[2][2] += a2 * b.z; acc[2][3] += a2 * b.w;
        acc[3][0] += a3 * b.x; acc[3][1] += a3 * b.y; acc[3][2] += a3 * b.z; acc[3][3] += a3 * b.w;
    }
    float4 bv = *(const float4*)&bias[tx * 4];
#pragma unroll
    for (int i = 0; i < 4; i++) {
        int row = m0 + ty * 4 + i;
        float4 hv = (row < M) ? *(const float4*)&h2[(size_t)row * 64 + tx * 4]
                              : make_float4(0.f, 0.f, 0.f, 0.f);
        float v0 = acc[i][0] + hv.x + bv.x;
        float v1 = acc[i][1] + hv.y + bv.y;
        float v2 = acc[i][2] + hv.z + bv.z;
        float v3 = acc[i][3] + hv.w + bv.w;
        v0 = v0 > 0.f ? v0 : expm1f(v0);
        v1 = v1 > 0.f ? v1 : expm1f(v1);
        v2 = v2 > 0.f ? v2 : expm1f(v2);
        v3 = v3 > 0.f ? v3 : expm1f(v3);
        acc[i][0] = v0; acc[i][1] = v1; acc[i][2] = v2; acc[i][3] = v3;
        rsum[ty * 4 + i][tx] = v0 + v1 + v2 + v3;
        rsq [ty * 4 + i][tx] = v0 * v0 + v1 * v1 + v2 * v2 + v3 * v3;
    }
    __syncthreads();
    if (t < 64) {
        float s = 0.f, q = 0.f;
#pragma unroll
        for (int j = 0; j < 16; j++) { s += rsum[t][j]; q += rsq[t][j]; }
        float mu = s * (1.f / 64.f);
        float var = q * (1.f / 64.f) - mu * mu;
        stats[t][0] = mu;
        stats[t][1] = rsqrtf(var + 1e-5f);
    }
    __syncthreads();
#pragma unroll
    for (int i = 0; i < 4; i++) {
        int row = m0 + ty * 4 + i;
        if (row < M) {
            float mu = stats[ty * 4 + i][0], sc = stats[ty * 4 + i][1];
            float4 o;
            o.x = (acc[i][0] - mu) * sc;
            o.y = (acc[i][1] - mu) * sc;
            o.z = (acc[i][2] - mu) * sc;
            o.w = (acc[i][3] - mu) * sc;
            *(float4*)&h3[(size_t)row * 64 + tx * 4] = o;
        }
    }
}

// ------------------------- pooling / head -------------------------
__global__ void k_pool(const float* __restrict__ x, const int* __restrict__ gid,
                       float* __restrict__ out, int N) {
    int i = blockIdx.x * blockDim.x + threadIdx.x;
    if (i < N * 64) {
        int node = i >> 6, f = i & 63;
        atomicAdd(&out[gid[node] * 64 + f], x[i]);
    }
}

__global__ void k_hg_update(const float* __restrict__ p, const float* __restrict__ W,
                            const float* __restrict__ b, float* __restrict__ hg) {
    int g = blockIdx.x, f = threadIdx.x;
    __shared__ float pr[64];
    pr[f] = p[g * 64 + f];
    __syncthreads();
    float s = b[f];
#pragma unroll 16
    for (int k = 0; k < 64; k++) s += pr[k] * W[k * 64 + f];
    s = s > 0.f ? s : 0.01f * s;
    hg[g * 64 + f] += s;
}

__global__ void k_mlp(const float* __restrict__ hg, const float* __restrict__ mW0,
                      const float* __restrict__ mb0, const float* __restrict__ mW1,
                      const float* __restrict__ mb1, const float* __restrict__ mW2,
                      const float* __restrict__ mb2, float* __restrict__ out) {
    int g = blockIdx.x;
    int t = threadIdx.x;
    __shared__ float x0[64], x1[256];
    if (t < 64) x0[t] = hg[g * 64 + t];
    __syncthreads();
    float s = mb0[t];
#pragma unroll 16
    for (int k = 0; k < 64; k++) s += x0[k] * mW0[k * 256 + t];
    x1[t] = fmaxf(s, 0.f);
    __syncthreads();
    s = mb1[t];
#pragma unroll 16
    for (int k = 0; k < 256; k++) s += x1[k] * mW1[k * 256 + t];
    float y = fmaxf(s, 0.f);
    __syncthreads();
    x1[t] = y;
    __syncthreads();
    s = mb2[t];
#pragma unroll 16
    for (int k = 0; k < 256; k++) s += x1[k] * mW2[k * 256 + t];
    out[g * 256 + t] = s;
}

// ------------------------- host launch -------------------------
extern "C" void kernel_launch(void* const* d_in, const int* in_sizes, int n_in,
                              void* d_out, int out_size) {
    const float* X     = (const float*)d_in[0];
    const int*   src   = (const int*)d_in[1];
    const int*   dst   = (const int*)d_in[2];
    const int*   gid   = (const int*)d_in[3];
    const float* projW = (const float*)d_in[4];
    const float* projb = (const float*)d_in[5];
    const float* fcW1  = (const float*)d_in[6];
    const float* al1   = (const float*)d_in[7];
    const float* ar1   = (const float*)d_in[8];
    const float* resW1 = (const float*)d_in[9];
    const float* b1    = (const float*)d_in[10];
    const float* fcW2  = (const float*)d_in[11];
    const float* al2   = (const float*)d_in[12];
    const float* ar2   = (const float*)d_in[13];
    const float* b2    = (const float*)d_in[14];
    const float* gW1   = (const float*)d_in[15];
    const float* gb1   = (const float*)d_in[16];
    const float* gW2   = (const float*)d_in[17];
    const float* gb2   = (const float*)d_in[18];
    const float* mW0   = (const float*)d_in[19];
    const float* mb0   = (const float*)d_in[20];
    const float* mW1   = (const float*)d_in[21];
    const float* mb1   = (const float*)d_in[22];
    const float* mW2   = (const float*)d_in[23];
    const float* mb2   = (const float*)d_in[24];
    float* out = (float*)d_out;

    int N = in_sizes[0] / HF;
    int E = in_sizes[1];
    if (N > NMAX) N = NMAX;
    if (E > EMAX) E = EMAX;

    float *p_h, *p_agg, *p_rst, *p_el, *p_er, *p_h2, *p_h3, *p_hg, *p_pool, *p_w;
    float *p_wl1, *p_wr1, *p_wl2, *p_wr2;
    int *p_indeg, *p_cursor, *p_rowptr, *p_srcs, *p_pos;
    cudaGetSymbolAddress((void**)&p_h, g_h);
    cudaGetSymbolAddress((void**)&p_agg, g_agg);
    cudaGetSymbolAddress((void**)&p_rst, g_rst);
    cudaGetSymbolAddress((void**)&p_el, g_el);
    cudaGetSymbolAddress((void**)&p_er, g_er);
    cudaGetSymbolAddress((void**)&p_h2, g_h2);
    cudaGetSymbolAddress((void**)&p_h3, g_h3);
    cudaGetSymbolAddress((void**)&p_hg, g_hg);
    cudaGetSymbolAddress((void**)&p_pool, g_pool);
    cudaGetSymbolAddress((void**)&p_w, g_w);
    cudaGetSymbolAddress((void**)&p_indeg, g_indeg);
    cudaGetSymbolAddress((void**)&p_cursor, g_cursor);
    cudaGetSymbolAddress((void**)&p_rowptr, g_rowptr);
    cudaGetSymbolAddress((void**)&p_srcs, g_srcs);
    cudaGetSymbolAddress((void**)&p_pos, g_pos);
    cudaGetSymbolAddress((void**)&p_wl1, g_wl1);
    cudaGetSymbolAddress((void**)&p_wr1, g_wr1);
    cudaGetSymbolAddress((void**)&p_wl2, g_wl2);
    cudaGetSymbolAddress((void**)&p_wr2, g_wr2);

    int rowTiles = (N + 63) / 64;
    int eBlocks = (E + 255) / 256;
    int nfBlocks = (N * 64 + 255) / 256;
    int nWarpBlocks = (N + 7) / 8;

    // --- CSR build ---
    k_zero_i<<<(N + 255) / 256, 256>>>(p_indeg, N);
    k_zero_i<<<(N + 255) / 256, 256>>>(p_cursor, N);
    k_zero_f<<<(GNUM * HF + 255) / 256, 256>>>(p_hg, GNUM * HF);
    k_hist<<<eBlocks, 256>>>(dst, p_indeg, E);
    k_scan<<<1, 1024>>>(p_indeg, p_rowptr, N);

    // --- attention projection vectors ---
    k_prep_w<8><<<2, 256>>>(fcW1, al1, ar1, p_wl1, p_wr1);
    k_prep_w<1><<<1, 64>>>(fcW2, al2, ar2, p_wl2, p_wr2);

    // --- projection + initial pooling ---
    k_gemm64<64, true><<<dim3(rowTiles, 1), 256>>>(X, projW, projb, p_h, N);
    k_pool<<<nfBlocks, 256>>>(p_h, gid, p_hg, N);

    // --- GAT layer 1 ---
    k_attn<8><<<nWarpBlocks, 256>>>(p_h, p_wl1, p_wr1, p_el, p_er, N);
    k_edge1_h8<<<eBlocks, 256>>>(src, dst, p_el, p_er, p_rowptr, p_cursor,
                                 p_srcs, p_pos, p_w, E);
    k_agg_h8<<<nWarpBlocks, 256>>>(p_srcs, p_h, p_w, p_rowptr, p_agg, N);
    k_gemm_cat1<<<dim3(rowTiles, 8), 256>>>(p_agg, p_h, fcW1, resW1, p_rst, N);
    k_epi1<<<N, 256>>>(p_rst, b1, p_h2, N);
    k_zero_f<<<(GNUM * HF + 255) / 256, 256>>>(p_pool, GNUM * HF);
    k_pool<<<nfBlocks, 256>>>(p_h2, gid, p_pool, N);
    k_hg_update<<<GNUM, 64>>>(p_pool, gW1, gb1, p_hg);

    // --- GAT layer 2 ---
    k_attn<1><<<nWarpBlocks, 256>>>(p_h2, p_wl2, p_wr2, p_el, p_er, N);
    k_edge2_h1<<<eBlocks, 256>>>(src, dst, p_el, p_er, p_pos, p_w, E);
    k_agg_h1<<<nWarpBlocks, 256>>>(p_srcs, p_h2, p_w, p_rowptr, p_agg, N);
    k_gemm_epi2<<<rowTiles, 256>>>(p_agg, fcW2, p_h2, b2, p_h3, N);
    k_zero_f<<<(GNUM * HF + 255) / 256, 256>>>(p_pool, GNUM * HF);
    k_pool<<<nfBlocks, 256>>>(p_h3, gid, p_pool, N);
    k_hg_update<<<GNUM, 64>>>(p_pool, gW2, gb2, p_hg);

    // --- MLP head ---
    k_mlp<<<GNUM, 256>>>(p_hg, mW0, mb0, mW1, mb1, mW2, mb2, out);
}